// round 14
// baseline (speedup 1.0000x reference)
#include <cuda_runtime.h>
#include <cuda_bf16.h>
#include <stdint.h>
#include <math.h>

// ---------------- problem constants ----------------
#define NTOT  4096
#define DIM   512
#define BHALF 2048
#define INV_TEMP 10.0f

// ---------------- GEMM tiling ----------------
#define BM 128
#define BN 128
#define BKC 64            // K elements per pipeline chunk (128 bytes/row)
#define NKCH (DIM / BKC)  // 8
#define NCHUNK 32         // 128-wide column chunks for partials
#define NTILES 528        // 32*33/2 triangular tiles
#define NPERS 264         // persistent CTAs, 2 tiles each; all co-resident (2/SM)
#define STAGE 32768       // bytes per pipeline stage (A 16KB + B 16KB)

// ---------------- device scratch (no allocs) ----------------
__device__ __nv_bfloat16 g_fb[NTOT * DIM];     // normalized features, bf16 (4 MB)
__device__ float g_part[NCHUNK * NTOT];        // per-(chunk,row) exp-sum partials
__device__ float g_pos[NTOT];                  // sim[i, (i+B)%N]
__device__ float g_blk[256];                   // finalize CTA partials
__device__ unsigned g_bcnt[2];                 // grid-barrier counters
__device__ unsigned g_bflag[2];                // grid-barrier release flags
__device__ unsigned g_ctr = 0;                 // finalize completion counter

// ---------------- helpers ----------------
static __device__ __forceinline__ uint32_t smem_u32(const void* p) {
    uint32_t a;
    asm("{ .reg .u64 t; cvta.to.shared.u64 t, %1; cvt.u32.u64 %0, t; }"
        : "=r"(a) : "l"(p));
    return a;
}

static __device__ __forceinline__ void ldm_x4(uint32_t r[4], uint32_t addr) {
    asm volatile("ldmatrix.sync.aligned.m8n8.x4.shared.b16 {%0,%1,%2,%3}, [%4];"
                 : "=r"(r[0]), "=r"(r[1]), "=r"(r[2]), "=r"(r[3]) : "r"(addr));
}

static __device__ __forceinline__ void mma16816(float c[4], const uint32_t a[4],
                                                uint32_t b0, uint32_t b1) {
    asm volatile(
        "mma.sync.aligned.m16n8k16.row.col.f32.bf16.bf16.f32 "
        "{%0,%1,%2,%3}, {%4,%5,%6,%7}, {%8,%9}, {%0,%1,%2,%3};"
        : "+f"(c[0]), "+f"(c[1]), "+f"(c[2]), "+f"(c[3])
        : "r"(a[0]), "r"(a[1]), "r"(a[2]), "r"(a[3]), "r"(b0), "r"(b1));
}

#define SWZ(off) ((off) ^ (((off) >> 3) & 0x70))

// Grid barrier for a fully co-resident grid. Flags are reset by the final
// reduction block so the kernel is graph-replay safe.
static __device__ __forceinline__ void grid_barrier(int i) {
    __syncthreads();
    if (threadIdx.x == 0) {
        __threadfence();                        // release my writes
        const unsigned old = atomicAdd(&g_bcnt[i], 1u);
        if (old == NPERS - 1) {
            atomicExch(&g_bflag[i], 1u);        // release everyone
        } else {
            while (atomicAdd(&g_bflag[i], 0u) == 0u) { __nanosleep(32); }
        }
        __threadfence();                        // acquire others' writes
    }
    __syncthreads();
}

// ---------------------------------------------------------------------------
// Chunk loader (diagonal tiles skip B and alias it to A)
// ---------------------------------------------------------------------------
static __device__ __forceinline__ void load_chunk_async(uint32_t sbase, int buf,
                                                        int tid, int row0, int col0,
                                                        int kc, bool diag) {
    const __nv_bfloat16* F = g_fb;
    const uint32_t A = sbase + buf * STAGE;
    const uint32_t B = A + 16384;
    const int k0 = kc * BKC;

    #pragma unroll
    for (int it = 0; it < 4; ++it) {
        int u = tid + it * 256;
        int r = u >> 3, cg = u & 7;
        uint32_t so = SWZ((uint32_t)(r * 128 + cg * 16));
        const void* g = F + (size_t)(row0 + r) * DIM + k0 + cg * 8;
        asm volatile("cp.async.cg.shared.global [%0], [%1], 16;" :: "r"(A + so), "l"(g));
    }
    if (!diag) {
        #pragma unroll
        for (int it = 0; it < 4; ++it) {
            int u = tid + it * 256;
            int r = u >> 3, cg = u & 7;
            uint32_t so = SWZ((uint32_t)(r * 128 + cg * 16));
            const void* g = F + (size_t)(col0 + r) * DIM + k0 + cg * 8;
            asm volatile("cp.async.cg.shared.global [%0], [%1], 16;" :: "r"(B + so), "l"(g));
        }
    }
    asm volatile("cp.async.commit_group;" ::: "memory");
}

// ---------------------------------------------------------------------------
// ONE fused persistent kernel: normalize -> barrier -> 2 GEMM tiles -> barrier
// -> finalize. 264 CTAs x 256 threads, all co-resident (2 CTA/SM).
// ---------------------------------------------------------------------------
__global__ void __launch_bounds__(256, 2) fused_kernel(const float* __restrict__ in,
                                                       float* __restrict__ out) {
    extern __shared__ char sm_raw[];
    __shared__ float nsm[32];          // normalize reduction slots (8 per iter)

    char* smem = (char*)(((uintptr_t)sm_raw + 1023) & ~(uintptr_t)1023);
    const uint32_t sbase = smem_u32(smem);

    const int tid = threadIdx.x;
    const int lane = tid & 31;
    const int wid = tid >> 5;

    // ================= Phase 1: normalize 16 rows per CTA =================
    {
        const int rloc = tid >> 6;          // 0..3
        const int g = tid & 63;             // 0..63
        #pragma unroll
        for (int it = 0; it < 4; ++it) {
            const int row = blockIdx.x * 16 + it * 4 + rloc;
            float4 v0, v1;
            float ss = 0.f;
            if (row < NTOT) {
                const float4* p = reinterpret_cast<const float4*>(in + (size_t)row * DIM);
                v0 = p[g];
                v1 = p[g + 64];
                ss = v0.x * v0.x + v0.y * v0.y + v0.z * v0.z + v0.w * v0.w +
                     v1.x * v1.x + v1.y * v1.y + v1.z * v1.z + v1.w * v1.w;
            }
            #pragma unroll
            for (int off = 16; off > 0; off >>= 1)
                ss += __shfl_xor_sync(0xffffffffu, ss, off);
            if (lane == 0) nsm[it * 8 + wid] = ss;
            __syncthreads();
            if (row < NTOT) {
                const float total = nsm[it * 8 + rloc * 2] + nsm[it * 8 + rloc * 2 + 1];
                const float scale = 1.0f / fmaxf(sqrtf(total), 1e-12f);
                __nv_bfloat162 a0 = __floats2bfloat162_rn(v0.x * scale, v0.y * scale);
                __nv_bfloat162 a1 = __floats2bfloat162_rn(v0.z * scale, v0.w * scale);
                __nv_bfloat162 b0 = __floats2bfloat162_rn(v1.x * scale, v1.y * scale);
                __nv_bfloat162 b1 = __floats2bfloat162_rn(v1.z * scale, v1.w * scale);
                uint2 oa, ob;
                oa.x = *reinterpret_cast<uint32_t*>(&a0);
                oa.y = *reinterpret_cast<uint32_t*>(&a1);
                ob.x = *reinterpret_cast<uint32_t*>(&b0);
                ob.y = *reinterpret_cast<uint32_t*>(&b1);
                *reinterpret_cast<uint2*>(g_fb + (size_t)row * DIM + g * 4) = oa;
                *reinterpret_cast<uint2*>(g_fb + (size_t)row * DIM + (g + 64) * 4) = ob;
            }
        }
    }

    grid_barrier(0);

    // ================= Phase 2: two GEMM tiles per CTA =================
    const int wm = wid & 3;           // 0..3: 32-row slice
    const int wn = wid >> 2;          // 0..1: 64-col slice
    const int aRow = wm * 32 + ((lane >> 3) & 1) * 8 + (lane & 7);
    const uint32_t aKoff = (uint32_t)((lane >> 4) * 16);
    const int bRow = wn * 64 + ((lane >> 4) & 1) * 8 + (lane & 7);
    const uint32_t bKoff = (uint32_t)(((lane >> 3) & 1) * 16);

    #pragma unroll 1
    for (int it2 = 0; it2 < 2; ++it2) {
        __syncthreads();   // protect epilogue scratch (in dyn smem) from reuse

        const int t = blockIdx.x + it2 * NPERS;
        int bx = (int)((sqrtf(8.0f * (float)t + 1.0f) - 1.0f) * 0.5f);
        while ((bx + 1) * (bx + 2) / 2 <= t) ++bx;
        while (bx * (bx + 1) / 2 > t) --bx;
        const int by = t - bx * (bx + 1) / 2;

        const int row0 = by * BM;
        const int col0 = bx * BN;
        const bool diag = (bx == by);
        const uint32_t bOff = diag ? 0u : 16384u;

        float acc[2][8][4];
        #pragma unroll
        for (int mi = 0; mi < 2; ++mi)
            #pragma unroll
            for (int ni = 0; ni < 8; ++ni)
                #pragma unroll
                for (int q = 0; q < 4; ++q) acc[mi][ni][q] = 0.f;

        load_chunk_async(sbase, 0, tid, row0, col0, 0, diag);
        load_chunk_async(sbase, 1, tid, row0, col0, 1, diag);

        #pragma unroll
        for (int c = 0; c < NKCH; ++c) {
            if (c < NKCH - 1) {
                asm volatile("cp.async.wait_group 1;" ::: "memory");
            } else {
                asm volatile("cp.async.wait_group 0;" ::: "memory");
            }
            __syncthreads();
            if (c + 2 < NKCH)
                load_chunk_async(sbase, (c + 2) % 3, tid, row0, col0, c + 2, diag);

            const uint32_t A = sbase + (c % 3) * STAGE;
            const uint32_t B = A + bOff;

            #pragma unroll
            for (int kk = 0; kk < 4; ++kk) {
                uint32_t a[2][4];
                #pragma unroll
                for (int mi = 0; mi < 2; ++mi) {
                    uint32_t off = (uint32_t)((aRow + mi * 16) * 128) + aKoff + kk * 32;
                    ldm_x4(a[mi], A + SWZ(off));
                }
                uint32_t bb[4][4];
                #pragma unroll
                for (int nb = 0; nb < 4; ++nb) {
                    uint32_t off = (uint32_t)((bRow + nb * 16) * 128) + bKoff + kk * 32;
                    ldm_x4(bb[nb], B + SWZ(off));
                }
                #pragma unroll
                for (int mi = 0; mi < 2; ++mi)
                    #pragma unroll
                    for (int ni = 0; ni < 8; ++ni)
                        mma16816(acc[mi][ni], a[mi],
                                 bb[ni >> 1][(ni & 1) * 2], bb[ni >> 1][(ni & 1) * 2 + 1]);
            }
        }

        // ---- epilogue (scratch aliases stage-0 dyn smem; safe: last compute
        //      reads stage 1, and the loop-top __syncthreads guards reuse) ----
        float* smem_row = reinterpret_cast<float*>(smem);          // [128][2]
        float* smem_col = reinterpret_cast<float*>(smem + 1024);   // [128][4]

        const int rbase = row0 + wm * 32;
        const int cbase = col0 + wn * 64;
        const bool isPosTile = (bx - by == 16);
        float erow[4] = {0.f, 0.f, 0.f, 0.f};

        #pragma unroll
        for (int ni = 0; ni < 8; ++ni) {
            #pragma unroll
            for (int q = 0; q < 2; ++q) {
                const int gj = cbase + ni * 8 + (lane & 3) * 2 + q;
                float ecol = 0.f;
                #pragma unroll
                for (int rg = 0; rg < 4; ++rg) {
                    const int mi = rg >> 1, half = rg & 1;
                    const float s = acc[mi][ni][half * 2 + q];
                    const int gi = rbase + mi * 16 + half * 8 + (lane >> 2);
                    if (isPosTile && gj == gi + BHALF) {
                        g_pos[gi] = s;
                        g_pos[gj] = s;
                    }
                    const float e = (gj != gi) ? __expf(INV_TEMP * s) : 0.f;
                    erow[rg] += e;
                    ecol += e;
                }
                ecol += __shfl_xor_sync(0xffffffffu, ecol, 4);
                ecol += __shfl_xor_sync(0xffffffffu, ecol, 8);
                ecol += __shfl_xor_sync(0xffffffffu, ecol, 16);
                if ((lane >> 2) == 0)
                    smem_col[(wn * 64 + ni * 8 + (lane & 3) * 2 + q) * 4 + wm] = ecol;
            }
        }

        #pragma unroll
        for (int rg = 0; rg < 4; ++rg) {
            float e = erow[rg];
            e += __shfl_xor_sync(0xffffffffu, e, 1);
            e += __shfl_xor_sync(0xffffffffu, e, 2);
            if ((lane & 3) == 0) {
                const int mi = rg >> 1, half = rg & 1;
                const int lr = wm * 32 + mi * 16 + half * 8 + (lane >> 2);
                smem_row[lr * 2 + wn] = e;
            }
        }
        __syncthreads();

        if (tid < 128) {
            const float pr = smem_row[tid * 2] + smem_row[tid * 2 + 1];
            g_part[(size_t)bx * NTOT + row0 + tid] = pr;
            if (!diag) {
                const float pc = smem_col[tid * 4 + 0] + smem_col[tid * 4 + 1] +
                                 smem_col[tid * 4 + 2] + smem_col[tid * 4 + 3];
                g_part[(size_t)by * NTOT + col0 + tid] = pc;
            }
        }
    }

    grid_barrier(1);

    // ================= Phase 3: finalize (CTAs 0..255) =================
    if (blockIdx.x >= 256) return;

    {
        const int row = blockIdx.x * 16 + (tid >> 4);   // 16 rows per CTA
        const int sub = tid & 15;                       // 16 threads per row

        float s = g_part[(size_t)(sub * 2 + 0) * NTOT + row] +
                  g_part[(size_t)(sub * 2 + 1) * NTOT + row];
        // reduce the 16 sub-sums (xor offsets stay within the 16-lane group)
        s += __shfl_xor_sync(0xffffffffu, s, 1);
        s += __shfl_xor_sync(0xffffffffu, s, 2);
        s += __shfl_xor_sync(0xffffffffu, s, 4);
        s += __shfl_xor_sync(0xffffffffu, s, 8);

        float local = (sub == 0) ? (logf(s) - INV_TEMP * g_pos[row]) : 0.f;
        // full-warp reduce sums this warp's two row losses (lanes 0 and 16)
        #pragma unroll
        for (int off = 16; off > 0; off >>= 1)
            local += __shfl_xor_sync(0xffffffffu, local, off);

        __shared__ float fsm[8];
        if (lane == 0) fsm[wid] = local;
        __syncthreads();

        if (tid == 0) {
            float bsum = 0.f;
            #pragma unroll
            for (int w = 0; w < 8; ++w) bsum += fsm[w];
            g_blk[blockIdx.x] = bsum;
            __threadfence();
            const unsigned old = atomicAdd(&g_ctr, 1u);
            if (old == 255u) {
                __threadfence();
                float tot = 0.f;
                for (int b = 0; b < 256; ++b) tot += g_blk[b];   // fixed order
                out[0] = tot / (float)NTOT;
                // reset ALL sync state for the next graph replay
                g_ctr = 0u;
                g_bcnt[0] = 0u; g_bcnt[1] = 0u;
                g_bflag[0] = 0u; g_bflag[1] = 0u;
                __threadfence();
            }
        }
    }
}

// ---------------------------------------------------------------------------
extern "C" void kernel_launch(void* const* d_in, const int* in_sizes, int n_in,
                              void* d_out, int out_size) {
    (void)in_sizes; (void)n_in; (void)out_size;
    const float* features = (const float*)d_in[0];
    float* out = (float*)d_out;

    const int dyn_smem = 3 * STAGE + 1024;   // 97 KB dynamic, 3-stage pipeline
    static bool attr_set = false;
    if (!attr_set) {
        cudaFuncSetAttribute(fused_kernel, cudaFuncAttributeMaxDynamicSharedMemorySize,
                             dyn_smem);
        attr_set = true;
    }

    fused_kernel<<<NPERS, 256, dyn_smem>>>(features, out);
}

// round 15
// speedup vs baseline: 1.2799x; 1.2799x over previous
#include <cuda_runtime.h>
#include <cuda_bf16.h>
#include <stdint.h>
#include <math.h>

// ---------------- problem constants ----------------
#define NTOT  4096
#define DIM   512
#define BHALF 2048
#define INV_TEMP 10.0f

// ---------------- GEMM tiling ----------------
#define BM 128
#define BN 128
#define BKC 64            // K elements per pipeline chunk (128 bytes/row)
#define NKCH (DIM / BKC)  // 8
#define NCHUNK 32         // 128-wide column chunks for partials
#define NTILES 528        // 32*33/2 triangular tiles
#define STAGE 32768       // bytes per pipeline stage (A 16KB + B 16KB)

// ---------------- device scratch (no allocs) ----------------
__device__ __nv_bfloat16 g_fb[NTOT * DIM];     // normalized features, bf16 (4 MB)
__device__ float g_part[NCHUNK * NTOT];        // per-(chunk,row) exp-sum partials
__device__ float g_pos[NTOT];                  // sim[i, (i+B)%N]
__device__ float g_blk[32];                    // finalize block partials
__device__ unsigned g_ctr = 0;                 // finalize completion counter

// ---------------- helpers ----------------
static __device__ __forceinline__ uint32_t smem_u32(const void* p) {
    uint32_t a;
    asm("{ .reg .u64 t; cvta.to.shared.u64 t, %1; cvt.u32.u64 %0, t; }"
        : "=r"(a) : "l"(p));
    return a;
}

static __device__ __forceinline__ void ldm_x4(uint32_t r[4], uint32_t addr) {
    asm volatile("ldmatrix.sync.aligned.m8n8.x4.shared.b16 {%0,%1,%2,%3}, [%4];"
                 : "=r"(r[0]), "=r"(r[1]), "=r"(r[2]), "=r"(r[3]) : "r"(addr));
}

static __device__ __forceinline__ void mma16816(float c[4], const uint32_t a[4],
                                                uint32_t b0, uint32_t b1) {
    asm volatile(
        "mma.sync.aligned.m16n8k16.row.col.f32.bf16.bf16.f32 "
        "{%0,%1,%2,%3}, {%4,%5,%6,%7}, {%8,%9}, {%0,%1,%2,%3};"
        : "+f"(c[0]), "+f"(c[1]), "+f"(c[2]), "+f"(c[3])
        : "r"(a[0]), "r"(a[1]), "r"(a[2]), "r"(a[3]), "r"(b0), "r"(b1));
}

#define SWZ(off) ((off) ^ (((off) >> 3) & 0x70))

// ---------------------------------------------------------------------------
// Kernel 1: L2-normalize rows -> bf16. 64 threads (2 warps) per row.
// grid = 1024 x 256 threads (4 rows per block).
// ---------------------------------------------------------------------------
__global__ __launch_bounds__(256) void normalize_kernel(const float* __restrict__ in) {
    const int tid = threadIdx.x;
    const int rloc = tid >> 6;              // 0..3: row within block
    const int g = tid & 63;                 // 0..63: lane within row-group
    const int row = blockIdx.x * 4 + rloc;
    const float4* p = reinterpret_cast<const float4*>(in + (size_t)row * DIM);

    float4 v0 = p[g];
    float4 v1 = p[g + 64];
    float ss = v0.x * v0.x + v0.y * v0.y + v0.z * v0.z + v0.w * v0.w +
               v1.x * v1.x + v1.y * v1.y + v1.z * v1.z + v1.w * v1.w;

    #pragma unroll
    for (int off = 16; off > 0; off >>= 1)
        ss += __shfl_xor_sync(0xffffffffu, ss, off);

    __shared__ float sm[8];
    if ((tid & 31) == 0) sm[tid >> 5] = ss;
    __syncthreads();
    const float total = sm[rloc * 2] + sm[rloc * 2 + 1];
    const float scale = 1.0f / fmaxf(sqrtf(total), 1e-12f);

    __nv_bfloat162 a0 = __floats2bfloat162_rn(v0.x * scale, v0.y * scale);
    __nv_bfloat162 a1 = __floats2bfloat162_rn(v0.z * scale, v0.w * scale);
    __nv_bfloat162 b0 = __floats2bfloat162_rn(v1.x * scale, v1.y * scale);
    __nv_bfloat162 b1 = __floats2bfloat162_rn(v1.z * scale, v1.w * scale);
    uint2 oa, ob;
    oa.x = *reinterpret_cast<uint32_t*>(&a0);
    oa.y = *reinterpret_cast<uint32_t*>(&a1);
    ob.x = *reinterpret_cast<uint32_t*>(&b0);
    ob.y = *reinterpret_cast<uint32_t*>(&b1);
    *reinterpret_cast<uint2*>(g_fb + (size_t)row * DIM + g * 4) = oa;
    *reinterpret_cast<uint2*>(g_fb + (size_t)row * DIM + (g + 64) * 4) = ob;
}

// ---------------------------------------------------------------------------
// Kernel 2: triangular bf16 HMMA GEMM (128x128 tiles, bx >= by) + dual-direction
// exp-sum epilogue. 3-stage cp.async pipeline, one sync per K-chunk.
// ---------------------------------------------------------------------------
static __device__ __forceinline__ void load_chunk_async(uint32_t sbase, int buf,
                                                        int tid, int row0, int col0,
                                                        int kc) {
    const __nv_bfloat16* F = g_fb;
    const uint32_t A = sbase + buf * STAGE;
    const uint32_t B = A + 16384;
    const int k0 = kc * BKC;

    #pragma unroll
    for (int it = 0; it < 4; ++it) {
        int u = tid + it * 256;
        int r = u >> 3, cg = u & 7;
        uint32_t so = SWZ((uint32_t)(r * 128 + cg * 16));
        const void* g = F + (size_t)(row0 + r) * DIM + k0 + cg * 8;
        asm volatile("cp.async.cg.shared.global [%0], [%1], 16;" :: "r"(A + so), "l"(g));
    }
    #pragma unroll
    for (int it = 0; it < 4; ++it) {
        int u = tid + it * 256;
        int r = u >> 3, cg = u & 7;
        uint32_t so = SWZ((uint32_t)(r * 128 + cg * 16));
        const void* g = F + (size_t)(col0 + r) * DIM + k0 + cg * 8;
        asm volatile("cp.async.cg.shared.global [%0], [%1], 16;" :: "r"(B + so), "l"(g));
    }
    asm volatile("cp.async.commit_group;" ::: "memory");
}

__global__ void __launch_bounds__(256, 2) sim_kernel() {
    extern __shared__ char sm_raw[];
    char* smem = (char*)(((uintptr_t)sm_raw + 1023) & ~(uintptr_t)1023);
    const uint32_t sbase = smem_u32(smem);

    // triangular decode: t -> (bx, by) with bx >= by, t = bx*(bx+1)/2 + by
    const int t = blockIdx.x;
    int bx = (int)((sqrtf(8.0f * (float)t + 1.0f) - 1.0f) * 0.5f);
    while ((bx + 1) * (bx + 2) / 2 <= t) ++bx;
    while (bx * (bx + 1) / 2 > t) --bx;
    const int by = t - bx * (bx + 1) / 2;

    const int tid = threadIdx.x;
    const int lane = tid & 31;
    const int wid = tid >> 5;
    const int wm = wid & 3;           // 0..3: 32-row slice
    const int wn = wid >> 2;          // 0..1: 64-col slice
    const int row0 = by * BM;
    const int col0 = bx * BN;

    float acc[2][8][4];
    #pragma unroll
    for (int mi = 0; mi < 2; ++mi)
        #pragma unroll
        for (int ni = 0; ni < 8; ++ni)
            #pragma unroll
            for (int q = 0; q < 4; ++q) acc[mi][ni][q] = 0.f;

    const int aRow = wm * 32 + ((lane >> 3) & 1) * 8 + (lane & 7);
    const uint32_t aKoff = (uint32_t)((lane >> 4) * 16);
    const int bRow = wn * 64 + ((lane >> 4) & 1) * 8 + (lane & 7);
    const uint32_t bKoff = (uint32_t)(((lane >> 3) & 1) * 16);

    // ---- 3-stage pipelined mainloop, one sync per chunk ----
    load_chunk_async(sbase, 0, tid, row0, col0, 0);
    load_chunk_async(sbase, 1, tid, row0, col0, 1);

    #pragma unroll
    for (int c = 0; c < NKCH; ++c) {
        if (c < NKCH - 1) {
            asm volatile("cp.async.wait_group 1;" ::: "memory");
        } else {
            asm volatile("cp.async.wait_group 0;" ::: "memory");
        }
        __syncthreads();
        if (c + 2 < NKCH)
            load_chunk_async(sbase, (c + 2) % 3, tid, row0, col0, c + 2);

        const uint32_t A = sbase + (c % 3) * STAGE;
        const uint32_t B = A + 16384;

        #pragma unroll
        for (int kk = 0; kk < 4; ++kk) {
            uint32_t a[2][4];
            #pragma unroll
            for (int mi = 0; mi < 2; ++mi) {
                uint32_t off = (uint32_t)((aRow + mi * 16) * 128) + aKoff + kk * 32;
                ldm_x4(a[mi], A + SWZ(off));
            }
            uint32_t bb[4][4];
            #pragma unroll
            for (int nb = 0; nb < 4; ++nb) {
                uint32_t off = (uint32_t)((bRow + nb * 16) * 128) + bKoff + kk * 32;
                ldm_x4(bb[nb], B + SWZ(off));
            }
            #pragma unroll
            for (int mi = 0; mi < 2; ++mi)
                #pragma unroll
                for (int ni = 0; ni < 8; ++ni)
                    mma16816(acc[mi][ni], a[mi],
                             bb[ni >> 1][(ni & 1) * 2], bb[ni >> 1][(ni & 1) * 2 + 1]);
        }
    }

    // ---- epilogue: row exp-sums + transposed column exp-sums ----
    float* smem_row = reinterpret_cast<float*>(smem);          // [128][2]
    float* smem_col = reinterpret_cast<float*>(smem + 1024);   // [128][4]

    const int rbase = row0 + wm * 32;
    const int cbase = col0 + wn * 64;
    const bool isPosTile = (bx - by == 16);
    float erow[4] = {0.f, 0.f, 0.f, 0.f};

    #pragma unroll
    for (int ni = 0; ni < 8; ++ni) {
        #pragma unroll
        for (int q = 0; q < 2; ++q) {
            const int gj = cbase + ni * 8 + (lane & 3) * 2 + q;
            float ecol = 0.f;
            #pragma unroll
            for (int rg = 0; rg < 4; ++rg) {
                const int mi = rg >> 1, half = rg & 1;
                const float s = acc[mi][ni][half * 2 + q];
                const int gi = rbase + mi * 16 + half * 8 + (lane >> 2);
                if (isPosTile && gj == gi + BHALF) {
                    g_pos[gi] = s;       // row gi's positive
                    g_pos[gj] = s;       // row gj's positive (symmetric)
                }
                const float e = (gj != gi) ? __expf(INV_TEMP * s) : 0.f;
                erow[rg] += e;
                ecol += e;
            }
            ecol += __shfl_xor_sync(0xffffffffu, ecol, 4);
            ecol += __shfl_xor_sync(0xffffffffu, ecol, 8);
            ecol += __shfl_xor_sync(0xffffffffu, ecol, 16);
            if ((lane >> 2) == 0)
                smem_col[(wn * 64 + ni * 8 + (lane & 3) * 2 + q) * 4 + wm] = ecol;
        }
    }

    #pragma unroll
    for (int rg = 0; rg < 4; ++rg) {
        float e = erow[rg];
        e += __shfl_xor_sync(0xffffffffu, e, 1);
        e += __shfl_xor_sync(0xffffffffu, e, 2);
        if ((lane & 3) == 0) {
            const int mi = rg >> 1, half = rg & 1;
            const int lr = wm * 32 + mi * 16 + half * 8 + (lane >> 2);
            smem_row[lr * 2 + wn] = e;
        }
    }
    __syncthreads();

    if (tid < 128) {
        const float pr = smem_row[tid * 2] + smem_row[tid * 2 + 1];
        g_part[(size_t)bx * NTOT + row0 + tid] = pr;
        if (bx != by) {
            const float pc = smem_col[tid * 4 + 0] + smem_col[tid * 4 + 1] +
                             smem_col[tid * 4 + 2] + smem_col[tid * 4 + 3];
            g_part[(size_t)by * NTOT + col0 + tid] = pc;
        }
    }
}

// ---------------------------------------------------------------------------
// Kernel 3: fused finalize. grid = 32 x 128 (one row per thread). Last block
// does the deterministic fixed-order final sum; counter self-resets.
// ---------------------------------------------------------------------------
__global__ __launch_bounds__(128) void finalize_kernel(float* __restrict__ out) {
    const int tid = threadIdx.x;
    const int row = blockIdx.x * 128 + tid;

    float s = 0.f;
    #pragma unroll
    for (int c = 0; c < NCHUNK; ++c)
        s += g_part[(size_t)c * NTOT + row];
    float local = logf(s) - INV_TEMP * g_pos[row];

    #pragma unroll
    for (int off = 16; off > 0; off >>= 1)
        local += __shfl_xor_sync(0xffffffffu, local, off);
    __shared__ float sm[4];
    if ((tid & 31) == 0) sm[tid >> 5] = local;
    __syncthreads();

    if (tid == 0) {
        float bsum = sm[0] + sm[1] + sm[2] + sm[3];
        g_blk[blockIdx.x] = bsum;
        __threadfence();
        const unsigned old = atomicAdd(&g_ctr, 1u);
        if (old == 31u) {
            __threadfence();
            float tot = 0.f;
            #pragma unroll
            for (int b = 0; b < 32; ++b) tot += g_blk[b];   // fixed order: deterministic
            out[0] = tot / (float)NTOT;
            g_ctr = 0u;   // reset for next graph replay
        }
    }
}

// ---------------------------------------------------------------------------
extern "C" void kernel_launch(void* const* d_in, const int* in_sizes, int n_in,
                              void* d_out, int out_size) {
    (void)in_sizes; (void)n_in; (void)out_size;
    const float* features = (const float*)d_in[0];
    float* out = (float*)d_out;

    const int dyn_smem = 3 * STAGE + 1024;   // 97 KB: 3-stage pipeline
    static bool attr_set = false;
    if (!attr_set) {
        cudaFuncSetAttribute(sim_kernel, cudaFuncAttributeMaxDynamicSharedMemorySize,
                             dyn_smem);
        attr_set = true;
    }

    normalize_kernel<<<NTOT / 4, 256>>>(features);
    sim_kernel<<<NTILES, 256, dyn_smem>>>();
    finalize_kernel<<<32, 128>>>(out);
}

// round 16
// speedup vs baseline: 1.2811x; 1.0009x over previous
#include <cuda_runtime.h>
#include <cuda_bf16.h>
#include <stdint.h>
#include <math.h>

// ---------------- problem constants ----------------
#define NTOT  4096
#define DIM   512
#define BHALF 2048
#define INV_TEMP 10.0f

// ---------------- GEMM tiling ----------------
#define BM 128
#define BN 128
#define BKC 64            // K elements per pipeline chunk (128 bytes/row)
#define NKCH (DIM / BKC)  // 8
#define NCHUNK 32         // 128-wide column chunks for partials
#define NTILES 528        // 32*33/2 triangular tiles
#define STAGE 32768       // bytes per pipeline stage (A 16KB + B 16KB)

// ---------------- device scratch (no allocs) ----------------
__device__ __nv_bfloat16 g_fb[NTOT * DIM];     // normalized features, bf16 (4 MB)
__device__ float g_part[NCHUNK * NTOT];        // per-(chunk,row) exp-sum partials
__device__ float g_pos[NTOT];                  // sim[i, (i+B)%N]
__device__ float g_blk[32];                    // finalize block partials
__device__ unsigned g_ctr = 0;                 // finalize completion counter

// ---------------- helpers ----------------
static __device__ __forceinline__ uint32_t smem_u32(const void* p) {
    uint32_t a;
    asm("{ .reg .u64 t; cvta.to.shared.u64 t, %1; cvt.u32.u64 %0, t; }"
        : "=r"(a) : "l"(p));
    return a;
}

static __device__ __forceinline__ void ldm_x4(uint32_t r[4], uint32_t addr) {
    asm volatile("ldmatrix.sync.aligned.m8n8.x4.shared.b16 {%0,%1,%2,%3}, [%4];"
                 : "=r"(r[0]), "=r"(r[1]), "=r"(r[2]), "=r"(r[3]) : "r"(addr));
}

static __device__ __forceinline__ void mma16816(float c[4], const uint32_t a[4],
                                                uint32_t b0, uint32_t b1) {
    asm volatile(
        "mma.sync.aligned.m16n8k16.row.col.f32.bf16.bf16.f32 "
        "{%0,%1,%2,%3}, {%4,%5,%6,%7}, {%8,%9}, {%0,%1,%2,%3};"
        : "+f"(c[0]), "+f"(c[1]), "+f"(c[2]), "+f"(c[3])
        : "r"(a[0]), "r"(a[1]), "r"(a[2]), "r"(a[3]), "r"(b0), "r"(b1));
}

#define SWZ(off) ((off) ^ (((off) >> 3) & 0x70))

// ---------------------------------------------------------------------------
// Kernel 1: L2-normalize rows -> bf16. 64 threads (2 warps) per row.
// grid = 1024 x 256 threads (4 rows per block).
// ---------------------------------------------------------------------------
__global__ __launch_bounds__(256) void normalize_kernel(const float* __restrict__ in) {
    const int tid = threadIdx.x;
    const int rloc = tid >> 6;              // 0..3: row within block
    const int g = tid & 63;                 // 0..63: lane within row-group
    const int row = blockIdx.x * 4 + rloc;
    const float4* p = reinterpret_cast<const float4*>(in + (size_t)row * DIM);

    float4 v0 = p[g];
    float4 v1 = p[g + 64];
    float ss = v0.x * v0.x + v0.y * v0.y + v0.z * v0.z + v0.w * v0.w +
               v1.x * v1.x + v1.y * v1.y + v1.z * v1.z + v1.w * v1.w;

    #pragma unroll
    for (int off = 16; off > 0; off >>= 1)
        ss += __shfl_xor_sync(0xffffffffu, ss, off);

    __shared__ float sm[8];
    if ((tid & 31) == 0) sm[tid >> 5] = ss;
    __syncthreads();
    const float total = sm[rloc * 2] + sm[rloc * 2 + 1];
    const float scale = 1.0f / fmaxf(sqrtf(total), 1e-12f);

    __nv_bfloat162 a0 = __floats2bfloat162_rn(v0.x * scale, v0.y * scale);
    __nv_bfloat162 a1 = __floats2bfloat162_rn(v0.z * scale, v0.w * scale);
    __nv_bfloat162 b0 = __floats2bfloat162_rn(v1.x * scale, v1.y * scale);
    __nv_bfloat162 b1 = __floats2bfloat162_rn(v1.z * scale, v1.w * scale);
    uint2 oa, ob;
    oa.x = *reinterpret_cast<uint32_t*>(&a0);
    oa.y = *reinterpret_cast<uint32_t*>(&a1);
    ob.x = *reinterpret_cast<uint32_t*>(&b0);
    ob.y = *reinterpret_cast<uint32_t*>(&b1);
    *reinterpret_cast<uint2*>(g_fb + (size_t)row * DIM + g * 4) = oa;
    *reinterpret_cast<uint2*>(g_fb + (size_t)row * DIM + (g + 64) * 4) = ob;
}

// ---------------------------------------------------------------------------
// Kernel 2: triangular bf16 HMMA GEMM (128x128 tiles, bx >= by) + dual-direction
// exp-sum epilogue. 3-stage cp.async pipeline, one sync per K-chunk.
// ---------------------------------------------------------------------------
static __device__ __forceinline__ void load_chunk_async(uint32_t sbase, int buf,
                                                        int tid, int row0, int col0,
                                                        int kc) {
    const __nv_bfloat16* F = g_fb;
    const uint32_t A = sbase + buf * STAGE;
    const uint32_t B = A + 16384;
    const int k0 = kc * BKC;

    #pragma unroll
    for (int it = 0; it < 4; ++it) {
        int u = tid + it * 256;
        int r = u >> 3, cg = u & 7;
        uint32_t so = SWZ((uint32_t)(r * 128 + cg * 16));
        const void* g = F + (size_t)(row0 + r) * DIM + k0 + cg * 8;
        asm volatile("cp.async.cg.shared.global [%0], [%1], 16;" :: "r"(A + so), "l"(g));
    }
    #pragma unroll
    for (int it = 0; it < 4; ++it) {
        int u = tid + it * 256;
        int r = u >> 3, cg = u & 7;
        uint32_t so = SWZ((uint32_t)(r * 128 + cg * 16));
        const void* g = F + (size_t)(col0 + r) * DIM + k0 + cg * 8;
        asm volatile("cp.async.cg.shared.global [%0], [%1], 16;" :: "r"(B + so), "l"(g));
    }
    asm volatile("cp.async.commit_group;" ::: "memory");
}

__global__ void __launch_bounds__(256, 2) sim_kernel() {
    extern __shared__ char sm_raw[];
    char* smem = (char*)(((uintptr_t)sm_raw + 1023) & ~(uintptr_t)1023);
    const uint32_t sbase = smem_u32(smem);

    // triangular decode: t -> (bx, by) with bx >= by, t = bx*(bx+1)/2 + by
    const int t = blockIdx.x;
    int bx = (int)((sqrtf(8.0f * (float)t + 1.0f) - 1.0f) * 0.5f);
    while ((bx + 1) * (bx + 2) / 2 <= t) ++bx;
    while (bx * (bx + 1) / 2 > t) --bx;
    const int by = t - bx * (bx + 1) / 2;

    const int tid = threadIdx.x;
    const int lane = tid & 31;
    const int wid = tid >> 5;
    const int wm = wid & 3;           // 0..3: 32-row slice
    const int wn = wid >> 2;          // 0..1: 64-col slice
    const int row0 = by * BM;
    const int col0 = bx * BN;

    float acc[2][8][4];
    #pragma unroll
    for (int mi = 0; mi < 2; ++mi)
        #pragma unroll
        for (int ni = 0; ni < 8; ++ni)
            #pragma unroll
            for (int q = 0; q < 4; ++q) acc[mi][ni][q] = 0.f;

    const int aRow = wm * 32 + ((lane >> 3) & 1) * 8 + (lane & 7);
    const uint32_t aKoff = (uint32_t)((lane >> 4) * 16);
    const int bRow = wn * 64 + ((lane >> 4) & 1) * 8 + (lane & 7);
    const uint32_t bKoff = (uint32_t)(((lane >> 3) & 1) * 16);

    // ---- 3-stage pipelined mainloop, one sync per chunk ----
    load_chunk_async(sbase, 0, tid, row0, col0, 0);
    load_chunk_async(sbase, 1, tid, row0, col0, 1);

    #pragma unroll
    for (int c = 0; c < NKCH; ++c) {
        if (c < NKCH - 1) {
            asm volatile("cp.async.wait_group 1;" ::: "memory");
        } else {
            asm volatile("cp.async.wait_group 0;" ::: "memory");
        }
        __syncthreads();
        if (c + 2 < NKCH)
            load_chunk_async(sbase, (c + 2) % 3, tid, row0, col0, c + 2);

        const uint32_t A = sbase + (c % 3) * STAGE;
        const uint32_t B = A + 16384;

        #pragma unroll
        for (int kk = 0; kk < 4; ++kk) {
            uint32_t a[2][4];
            #pragma unroll
            for (int mi = 0; mi < 2; ++mi) {
                uint32_t off = (uint32_t)((aRow + mi * 16) * 128) + aKoff + kk * 32;
                ldm_x4(a[mi], A + SWZ(off));
            }
            uint32_t bb[4][4];
            #pragma unroll
            for (int nb = 0; nb < 4; ++nb) {
                uint32_t off = (uint32_t)((bRow + nb * 16) * 128) + bKoff + kk * 32;
                ldm_x4(bb[nb], B + SWZ(off));
            }
            #pragma unroll
            for (int mi = 0; mi < 2; ++mi)
                #pragma unroll
                for (int ni = 0; ni < 8; ++ni)
                    mma16816(acc[mi][ni], a[mi],
                             bb[ni >> 1][(ni & 1) * 2], bb[ni >> 1][(ni & 1) * 2 + 1]);
        }
    }

    // ---- epilogue: row exp-sums + transposed column exp-sums ----
    float* smem_row = reinterpret_cast<float*>(smem);          // [128][2]
    float* smem_col = reinterpret_cast<float*>(smem + 1024);   // [128][4]

    const int rbase = row0 + wm * 32;
    const int cbase = col0 + wn * 64;
    const bool isPosTile = (bx - by == 16);
    float erow[4] = {0.f, 0.f, 0.f, 0.f};

    #pragma unroll
    for (int ni = 0; ni < 8; ++ni) {
        #pragma unroll
        for (int q = 0; q < 2; ++q) {
            const int gj = cbase + ni * 8 + (lane & 3) * 2 + q;
            float ecol = 0.f;
            #pragma unroll
            for (int rg = 0; rg < 4; ++rg) {
                const int mi = rg >> 1, half = rg & 1;
                const float s = acc[mi][ni][half * 2 + q];
                const int gi = rbase + mi * 16 + half * 8 + (lane >> 2);
                if (isPosTile && gj == gi + BHALF) {
                    g_pos[gi] = s;       // row gi's positive
                    g_pos[gj] = s;       // row gj's positive (symmetric)
                }
                const float e = (gj != gi) ? __expf(INV_TEMP * s) : 0.f;
                erow[rg] += e;
                ecol += e;
            }
            ecol += __shfl_xor_sync(0xffffffffu, ecol, 4);
            ecol += __shfl_xor_sync(0xffffffffu, ecol, 8);
            ecol += __shfl_xor_sync(0xffffffffu, ecol, 16);
            if ((lane >> 2) == 0)
                smem_col[(wn * 64 + ni * 8 + (lane & 3) * 2 + q) * 4 + wm] = ecol;
        }
    }

    #pragma unroll
    for (int rg = 0; rg < 4; ++rg) {
        float e = erow[rg];
        e += __shfl_xor_sync(0xffffffffu, e, 1);
        e += __shfl_xor_sync(0xffffffffu, e, 2);
        if ((lane & 3) == 0) {
            const int mi = rg >> 1, half = rg & 1;
            const int lr = wm * 32 + mi * 16 + half * 8 + (lane >> 2);
            smem_row[lr * 2 + wn] = e;
        }
    }
    __syncthreads();

    if (tid < 128) {
        const float pr = smem_row[tid * 2] + smem_row[tid * 2 + 1];
        g_part[(size_t)bx * NTOT + row0 + tid] = pr;
        if (bx != by) {
            const float pc = smem_col[tid * 4 + 0] + smem_col[tid * 4 + 1] +
                             smem_col[tid * 4 + 2] + smem_col[tid * 4 + 3];
            g_part[(size_t)by * NTOT + col0 + tid] = pc;
        }
    }
}

// ---------------------------------------------------------------------------
// Kernel 3: fused finalize. grid = 32 x 128 (one row per thread). Last block
// does the deterministic fixed-order final sum; counter self-resets.
// ---------------------------------------------------------------------------
__global__ __launch_bounds__(128) void finalize_kernel(float* __restrict__ out) {
    const int tid = threadIdx.x;
    const int row = blockIdx.x * 128 + tid;

    float s = 0.f;
    #pragma unroll
    for (int c = 0; c < NCHUNK; ++c)
        s += g_part[(size_t)c * NTOT + row];
    float local = logf(s) - INV_TEMP * g_pos[row];

    #pragma unroll
    for (int off = 16; off > 0; off >>= 1)
        local += __shfl_xor_sync(0xffffffffu, local, off);
    __shared__ float sm[4];
    if ((tid & 31) == 0) sm[tid >> 5] = local;
    __syncthreads();

    if (tid == 0) {
        float bsum = sm[0] + sm[1] + sm[2] + sm[3];
        g_blk[blockIdx.x] = bsum;
        __threadfence();
        const unsigned old = atomicAdd(&g_ctr, 1u);
        if (old == 31u) {
            __threadfence();
            float tot = 0.f;
            #pragma unroll
            for (int b = 0; b < 32; ++b) tot += g_blk[b];   // fixed order: deterministic
            out[0] = tot / (float)NTOT;
            g_ctr = 0u;   // reset for next graph replay
        }
    }
}

// ---------------------------------------------------------------------------
extern "C" void kernel_launch(void* const* d_in, const int* in_sizes, int n_in,
                              void* d_out, int out_size) {
    (void)in_sizes; (void)n_in; (void)out_size;
    const float* features = (const float*)d_in[0];
    float* out = (float*)d_out;

    const int dyn_smem = 3 * STAGE + 1024;   // 97 KB: 3-stage pipeline
    static bool attr_set = false;
    if (!attr_set) {
        cudaFuncSetAttribute(sim_kernel, cudaFuncAttributeMaxDynamicSharedMemorySize,
                             dyn_smem);
        attr_set = true;
    }

    normalize_kernel<<<NTOT / 4, 256>>>(features);
    sim_kernel<<<NTILES, 256, dyn_smem>>>();
    finalize_kernel<<<32, 128>>>(out);
}